// round 1
// baseline (speedup 1.0000x reference)
#include <cuda_runtime.h>
#include <cstddef>

#define NN 50000
#define EE 800000
#define ET (EE + NN)
#define BB 50
#define FIN 16
#define HIDC 64
#define NH 4
#define C256 256
#define EDGE_BLOCKS ((EE + 255) / 256)

// ------------------------- device scratch (static, no allocs) -------------------------
__device__ float g_ew[EE];
__device__ float g_ewpart[EDGE_BLOCKS];
__device__ float g_ew_sum;
__device__ int   g_deg[NN];
__device__ int   g_off[NN + 1];
__device__ int   g_cursor[NN];
__device__ int   g_bsum[64];
__device__ int   g_csr_src[ET];
__device__ float g_csr_ew[ET];
__device__ float g_h[(size_t)NN * C256];
__device__ float g_as[NN * NH];
__device__ float g_ad[NN * NH];
__device__ float g_x0[NN * HIDC];
__device__ float g_x1[NN * HIDC];
__device__ float g_vs[HIDC * NH];
__device__ float g_vd[HIDC * NH];
__device__ float g_ce[NH];

__device__ __forceinline__ float elu1(float x)  { return x > 0.f ? x : __expf(x) - 1.f; }
__device__ __forceinline__ float lrelu(float x) { return x > 0.f ? x : 0.2f * x; }

// ------------------------- init -------------------------
__global__ void k_init() {
    int i = blockIdx.x * blockDim.x + threadIdx.x;
    if (i < NN) g_deg[i] = 0;
    if (i == 0) g_ew_sum = 0.f;
}

// ------------------------- edge encoder + dst histogram -------------------------
__global__ void __launch_bounds__(256) k_edge(
    const float* __restrict__ ea, const int* __restrict__ dst,
    const float* __restrict__ w1, const float* __restrict__ b1,
    const float* __restrict__ w2, const float* __restrict__ b2)
{
    __shared__ float ws[448];
    __shared__ float red[8];
    int tid = threadIdx.x;
    for (int i = tid; i < 448; i += 256)
        ws[i] = (i < 320) ? w1[i] : (i < 384) ? b1[i - 320] : w2[i - 384];
    __syncthreads();

    int e = blockIdx.x * 256 + tid;
    float val = 0.f;
    if (e < EE) {
        float a0 = ea[e*5+0], a1 = ea[e*5+1], a2 = ea[e*5+2], a3 = ea[e*5+3], a4 = ea[e*5+4];
        float acc = __ldg(b2);
        #pragma unroll 8
        for (int j = 0; j < 64; j++) {
            float t = ws[320+j] + a0*ws[j] + a1*ws[64+j] + a2*ws[128+j] + a3*ws[192+j] + a4*ws[256+j];
            t = fmaxf(t, 0.f);
            acc += t * ws[384+j];
        }
        val = 1.f / (1.f + __expf(-acc));
        g_ew[e] = val;
        atomicAdd(&g_deg[dst[e]], 1);
    }
    // deterministic block-partial sum
    float s = val;
    #pragma unroll
    for (int o = 16; o; o >>= 1) s += __shfl_xor_sync(0xffffffffu, s, o);
    if ((tid & 31) == 0) red[tid >> 5] = s;
    __syncthreads();
    if (tid == 0) {
        float t = 0.f;
        for (int w = 0; w < 8; w++) t += red[w];
        g_ewpart[blockIdx.x] = t;
    }
}

__global__ void k_ewred() {
    __shared__ float red[32];
    int tid = threadIdx.x;
    float s = 0.f;
    for (int i = tid; i < EDGE_BLOCKS; i += 1024) s += g_ewpart[i];
    #pragma unroll
    for (int o = 16; o; o >>= 1) s += __shfl_xor_sync(0xffffffffu, s, o);
    if ((tid & 31) == 0) red[tid >> 5] = s;
    __syncthreads();
    if (tid == 0) {
        float t = 0.f;
        for (int w = 0; w < 32; w++) t += red[w];
        g_ew_sum = t;
    }
}

// ------------------------- CSR build: scan + scatter -------------------------
__global__ void k_scan1() {
    __shared__ int wsum[32];
    int tid = threadIdx.x, lane = tid & 31, w = tid >> 5;
    int i = blockIdx.x * 1024 + tid;
    int x = (i < NN) ? g_deg[i] + 1 : 0;  // +1 for self-loop
    #pragma unroll
    for (int d = 1; d < 32; d <<= 1) {
        int y = __shfl_up_sync(0xffffffffu, x, d);
        if (lane >= d) x += y;
    }
    if (lane == 31) wsum[w] = x;
    __syncthreads();
    if (w == 0) {
        int y = wsum[lane];
        #pragma unroll
        for (int d = 1; d < 32; d <<= 1) {
            int z = __shfl_up_sync(0xffffffffu, y, d);
            if (lane >= d) y += z;
        }
        wsum[lane] = y;
    }
    __syncthreads();
    if (w) x += wsum[w - 1];
    if (i < NN) g_off[i + 1] = x;
    if (tid == 1023) g_bsum[blockIdx.x] = x;
}

__global__ void k_scan2() {
    int running = 0;
    for (int b = 0; b < 49; b++) { int t = g_bsum[b]; g_bsum[b] = running; running += t; }
}

__global__ void k_scan3() {
    int i = blockIdx.x * 1024 + threadIdx.x;
    if (i < NN) g_off[i + 1] += g_bsum[blockIdx.x];
    if (i == 0) g_off[0] = 0;
}

__global__ void k_cursor() {
    int i = blockIdx.x * blockDim.x + threadIdx.x;
    if (i < NN) g_cursor[i] = g_off[i];
}

__global__ void k_scatter(const int* __restrict__ src, const int* __restrict__ dst) {
    int e = blockIdx.x * 256 + threadIdx.x;
    if (e >= EE) return;
    int d = dst[e];
    int p = atomicAdd(&g_cursor[d], 1);
    g_csr_src[p] = src[e];
    g_csr_ew[p]  = g_ew[e];
}

__global__ void k_selfloop() {
    int n = blockIdx.x * blockDim.x + threadIdx.x;
    if (n >= NN) return;
    int p = g_off[n + 1] - 1;
    g_csr_src[p] = n;
    g_csr_ew[p]  = g_ew_sum * (1.f / EE);
}

// ------------------------- per-conv prep: fold att dots into GEMM columns -------------------------
__global__ void k_prep(const float* __restrict__ W, const float* __restrict__ aS,
                       const float* __restrict__ aD, const float* __restrict__ We,
                       const float* __restrict__ aE, int K)
{
    int t = threadIdx.x;
    int k = t >> 2, h = t & 3;
    if (k < K) {
        float s = 0.f, d = 0.f;
        for (int c = 0; c < 64; c++) {
            float wv = W[k * 256 + h * 64 + c];
            s += wv * aS[h * 64 + c];
            d += wv * aD[h * 64 + c];
        }
        g_vs[k * 4 + h] = s;
        g_vd[k * 4 + h] = d;
    }
    if (t < 4) {
        float ce = 0.f;
        for (int c = 0; c < 64; c++) ce += We[t * 64 + c] * aE[t * 64 + c];
        g_ce[t] = ce;
    }
}

// ------------------------- node GEMM: h = xi@W, + fused alpha_src/alpha_dst -------------------------
template <int K>
__global__ void __launch_bounds__(288) k_gemm(int which, const float* __restrict__ xin_ext,
                                              const float* __restrict__ W)
{
    const float* __restrict__ xin = (which == 0) ? g_x0 : (which == 1) ? g_x1 : xin_ext;
    __shared__ float xs[32 * K];
    int tid = threadIdx.x;
    int node0 = blockIdx.x * 32;
    int base = node0 * K;
    for (int i = tid; i < 32 * K; i += 288) {
        int gi = base + i;
        xs[i] = (gi < NN * K) ? xin[gi] : 0.f;
    }
    __syncthreads();

    if (tid < 256) {
        float wreg[K];
        #pragma unroll
        for (int k = 0; k < K; k++) wreg[k] = W[k * 256 + tid];
        for (int nn = 0; nn < 32; nn++) {
            int node = node0 + nn;
            if (node >= NN) break;
            const float4* x4 = (const float4*)(xs + nn * K);
            float acc = 0.f;
            #pragma unroll
            for (int k4 = 0; k4 < K / 4; k4++) {
                float4 v = x4[k4];
                acc += v.x * wreg[4*k4] + v.y * wreg[4*k4+1] + v.z * wreg[4*k4+2] + v.w * wreg[4*k4+3];
            }
            g_h[(size_t)node * 256 + tid] = acc;
        }
    } else {
        int t2 = tid - 256;
        int role = t2 & 7, h = role & 3, nsub = t2 >> 3;
        const float* v = (role & 4) ? g_vd : g_vs;
        float* outp = (role & 4) ? g_ad : g_as;
        for (int nn = nsub; nn < 32; nn += 4) {
            int node = node0 + nn;
            if (node >= NN) continue;
            float a = 0.f;
            #pragma unroll
            for (int k = 0; k < K; k++) a += xs[nn * K + k] * v[k * 4 + h];
            outp[node * 4 + h] = a;
        }
    }
}

// ------------------------- warp-per-node GAT aggregation (online softmax) -------------------------
__device__ __forceinline__ void warp_agg(int n, int lane, int* s_sm, float4* p_sm, float r[8])
{
    const unsigned F = 0xffffffffu;
    int start = g_off[n], end = g_off[n + 1];
    float4 adv = *(const float4*)(g_ad + n * 4);
    float ce0 = g_ce[0], ce1 = g_ce[1], ce2 = g_ce[2], ce3 = g_ce[3];
    int head = lane >> 3;

    float m0 = -1e30f, m1 = -1e30f, m2 = -1e30f, m3 = -1e30f;
    float sl0 = 0.f, sl1 = 0.f, sl2 = 0.f, sl3 = 0.f;
    float acc[8];
    #pragma unroll
    for (int j = 0; j < 8; j++) acc[j] = 0.f;

    for (int base = start; base < end; base += 32) {
        int i = base + lane;
        bool v = i < end;
        int s = v ? g_csr_src[i] : 0;
        float w = v ? g_csr_ew[i] : 0.f;
        float4 asv = *(const float4*)(g_as + s * 4);
        float a0 = v ? lrelu(asv.x + adv.x + w * ce0) : -1e30f;
        float a1 = v ? lrelu(asv.y + adv.y + w * ce1) : -1e30f;
        float a2 = v ? lrelu(asv.z + adv.z + w * ce2) : -1e30f;
        float a3 = v ? lrelu(asv.w + adv.w + w * ce3) : -1e30f;

        float c0 = a0, c1 = a1, c2 = a2, c3 = a3;
        #pragma unroll
        for (int o = 16; o; o >>= 1) {
            c0 = fmaxf(c0, __shfl_xor_sync(F, c0, o));
            c1 = fmaxf(c1, __shfl_xor_sync(F, c1, o));
            c2 = fmaxf(c2, __shfl_xor_sync(F, c2, o));
            c3 = fmaxf(c3, __shfl_xor_sync(F, c3, o));
        }
        float nm0 = fmaxf(m0, c0), nm1 = fmaxf(m1, c1), nm2 = fmaxf(m2, c2), nm3 = fmaxf(m3, c3);
        float sc0 = __expf(m0 - nm0), sc1 = __expf(m1 - nm1);
        float sc2 = __expf(m2 - nm2), sc3 = __expf(m3 - nm3);
        float p0 = v ? __expf(a0 - nm0) : 0.f;
        float p1 = v ? __expf(a1 - nm1) : 0.f;
        float p2 = v ? __expf(a2 - nm2) : 0.f;
        float p3 = v ? __expf(a3 - nm3) : 0.f;
        sl0 = sl0 * sc0 + p0; sl1 = sl1 * sc1 + p1;
        sl2 = sl2 * sc2 + p2; sl3 = sl3 * sc3 + p3;
        m0 = nm0; m1 = nm1; m2 = nm2; m3 = nm3;

        float mySc = (lane & 16) ? ((lane & 8) ? sc3 : sc2) : ((lane & 8) ? sc1 : sc0);
        #pragma unroll
        for (int j = 0; j < 8; j++) acc[j] *= mySc;

        s_sm[lane] = s;
        p_sm[lane] = make_float4(p0, p1, p2, p3);
        __syncwarp();
        int cnt = min(32, end - base);
        for (int kk = 0; kk < cnt; kk++) {
            int sk = s_sm[kk];
            float pk = ((const float*)p_sm)[kk * 4 + head];
            const float4* hp = (const float4*)(g_h + (size_t)sk * 256 + lane * 8);
            float4 h0 = hp[0], h1 = hp[1];
            acc[0] += pk * h0.x; acc[1] += pk * h0.y; acc[2] += pk * h0.z; acc[3] += pk * h0.w;
            acc[4] += pk * h1.x; acc[5] += pk * h1.y; acc[6] += pk * h1.z; acc[7] += pk * h1.w;
        }
        __syncwarp();
    }

    #pragma unroll
    for (int o = 16; o; o >>= 1) {
        sl0 += __shfl_xor_sync(F, sl0, o);
        sl1 += __shfl_xor_sync(F, sl1, o);
        sl2 += __shfl_xor_sync(F, sl2, o);
        sl3 += __shfl_xor_sync(F, sl3, o);
    }
    float myS = (lane & 16) ? ((lane & 8) ? sl3 : sl2) : ((lane & 8) ? sl1 : sl0);
    float inv = 1.f / (myS + 1e-16f);
    #pragma unroll
    for (int j = 0; j < 8; j++) {
        float vv = acc[j] * inv;
        vv += __shfl_xor_sync(F, vv, 8);
        vv += __shfl_xor_sync(F, vv, 16);
        r[j] = vv;  // head-sum for channel (lane&7)*8+j
    }
}

__global__ void __launch_bounds__(256) k_agg(int mode, const float* __restrict__ bias)
{
    __shared__ int s_sm[8][32];
    __shared__ float4 p_sm[8][32];
    int lane = threadIdx.x & 31, w = threadIdx.x >> 5;
    int n = blockIdx.x * 8 + w;
    if (n >= NN) return;
    float r[8];
    warp_agg(n, lane, s_sm[w], p_sm[w], r);
    if (lane < 8) {
        const float* res = mode ? g_x0 : nullptr;
        float* outp = mode ? g_x1 : g_x0;
        float o[8];
        #pragma unroll
        for (int j = 0; j < 8; j++) {
            int c = lane * 8 + j;
            float val = 0.25f * r[j] + __ldg(bias + c);
            if (res) val += res[(size_t)n * 64 + c];
            o[j] = elu1(val);
        }
        float4* op = (float4*)(outp + (size_t)n * 64 + lane * 8);
        op[0] = make_float4(o[0], o[1], o[2], o[3]);
        op[1] = make_float4(o[4], o[5], o[6], o[7]);
    }
}

// ------------------------- conv3 @ targets + LayerNorm + MLP readout -------------------------
__global__ void __launch_bounds__(32) k_final(
    const int* __restrict__ batch, const float* __restrict__ bias,
    const float* __restrict__ lng, const float* __restrict__ lnb,
    const float* __restrict__ l1w, const float* __restrict__ l1b,
    const float* __restrict__ l2w, const float* __restrict__ l2b,
    float* __restrict__ out)
{
    __shared__ int s_sm[32];
    __shared__ float4 p_sm[32];
    __shared__ float xbuf[64], tbuf[64];
    const unsigned F = 0xffffffffu;
    int lane = threadIdx.x;
    int b = blockIdx.x;

    // searchsorted(batch, b) 'left'
    int lo = 0, hi = NN;
    while (lo < hi) {
        int mid = (lo + hi) >> 1;
        if (batch[mid] < b) lo = mid + 1; else hi = mid;
    }
    int n = lo;

    float r[8];
    warp_agg(n, lane, s_sm, p_sm, r);
    if (lane < 8) {
        #pragma unroll
        for (int j = 0; j < 8; j++) {
            int c = lane * 8 + j;
            float val = 0.25f * r[j] + bias[c] + g_x1[(size_t)n * 64 + c];
            xbuf[c] = elu1(val);
        }
    }
    __syncwarp();

    float v0 = xbuf[lane], v1 = xbuf[lane + 32];
    float sum = v0 + v1;
    #pragma unroll
    for (int o = 16; o; o >>= 1) sum += __shfl_xor_sync(F, sum, o);
    float mean = sum * (1.f / 64.f);
    float d0 = v0 - mean, d1 = v1 - mean;
    float vs = d0 * d0 + d1 * d1;
    #pragma unroll
    for (int o = 16; o; o >>= 1) vs += __shfl_xor_sync(F, vs, o);
    float rstd = rsqrtf(vs * (1.f / 64.f) + 1e-5f);
    xbuf[lane]      = d0 * rstd * lng[lane]      + lnb[lane];
    xbuf[lane + 32] = d1 * rstd * lng[lane + 32] + lnb[lane + 32];
    __syncwarp();

    float a0 = l1b[lane], a1 = l1b[lane + 32];
    for (int c = 0; c < 64; c++) {
        float xv = xbuf[c];
        a0 += xv * l1w[c * 64 + lane];
        a1 += xv * l1w[c * 64 + lane + 32];
    }
    tbuf[lane]      = elu1(a0);
    tbuf[lane + 32] = elu1(a1);
    __syncwarp();

    if (lane < 3) {
        float o = l2b[lane];
        for (int c = 0; c < 64; c++) o += tbuf[c] * l2w[c * 3 + lane];
        out[b * 3 + lane] = o;
    }
}

// ------------------------- launch -------------------------
extern "C" void kernel_launch(void* const* d_in, const int* in_sizes, int n_in,
                              void* d_out, int out_size)
{
    const float* x      = (const float*)d_in[0];
    const int*   ei     = (const int*)  d_in[1];
    const float* eattr  = (const float*)d_in[2];
    const int*   batch  = (const int*)  d_in[3];
    const float* ee_w1  = (const float*)d_in[4];
    const float* ee_b1  = (const float*)d_in[5];
    const float* ee_w2  = (const float*)d_in[6];
    const float* ee_b2  = (const float*)d_in[7];
    const float* W1     = (const float*)d_in[8];
    const float* Ws     = (const float*)d_in[9];
    const float* att_s  = (const float*)d_in[10];
    const float* att_d  = (const float*)d_in[11];
    const float* We     = (const float*)d_in[12];
    const float* att_e  = (const float*)d_in[13];
    const float* bias   = (const float*)d_in[14];
    const float* lng    = (const float*)d_in[15];
    const float* lnb    = (const float*)d_in[16];
    const float* l1w    = (const float*)d_in[17];
    const float* l1b    = (const float*)d_in[18];
    const float* l2w    = (const float*)d_in[19];
    const float* l2b    = (const float*)d_in[20];
    float* out = (float*)d_out;

    const int* src = ei;
    const int* dst = ei + EE;

    k_init<<<(NN + 255) / 256, 256>>>();
    k_edge<<<EDGE_BLOCKS, 256>>>(eattr, dst, ee_w1, ee_b1, ee_w2, ee_b2);
    k_ewred<<<1, 1024>>>();
    k_scan1<<<49, 1024>>>();
    k_scan2<<<1, 1>>>();
    k_scan3<<<49, 1024>>>();
    k_cursor<<<(NN + 255) / 256, 256>>>();
    k_scatter<<<EDGE_BLOCKS, 256>>>(src, dst);
    k_selfloop<<<(NN + 255) / 256, 256>>>();

    const int gemm_grid = (NN + 31) / 32;
    const int agg_grid  = (NN + 7) / 8;

    // conv1: x [N,16] -> xi0
    k_prep<<<1, 256>>>(W1, att_s, att_d, We, att_e, FIN);
    k_gemm<FIN><<<gemm_grid, 288>>>(-1, x, W1);
    k_agg<<<agg_grid, 256>>>(0, bias);

    // conv2 (residual): xi0 -> xi1
    k_prep<<<1, 256>>>(Ws, att_s + 256, att_d + 256, We + 256, att_e + 256, HIDC);
    k_gemm<HIDC><<<gemm_grid, 288>>>(0, nullptr, Ws);
    k_agg<<<agg_grid, 256>>>(1, bias + 64);

    // conv3 (residual) only at the 50 readout targets, fused with LN + MLP
    k_prep<<<1, 256>>>(Ws + 64 * 256, att_s + 512, att_d + 512, We + 512, att_e + 512, HIDC);
    k_gemm<HIDC><<<gemm_grid, 288>>>(1, nullptr, Ws + 64 * 256);
    k_final<<<BB, 32>>>(batch, bias + 128, lng, lnb, l1w, l1b, l2w, l2b, out);
}

// round 2
// speedup vs baseline: 1.4247x; 1.4247x over previous
#include <cuda_runtime.h>
#include <cuda_fp16.h>
#include <cstddef>

#define NN 50000
#define EE 800000
#define ET (EE + NN)
#define BB 50
#define FIN 16
#define HIDC 64
#define NH 4
#define C256 256
#define CAP 32768
#define EDGE_BLOCKS ((EE + 255) / 256)

// ------------------------- device scratch (static, no allocs) -------------------------
__device__ float g_ew[EE];
__device__ float g_ewpart[EDGE_BLOCKS];
__device__ float g_ew_sum;
__device__ int   g_deg[NN];
__device__ int   g_off[NN + 1];
__device__ int   g_cursor[NN];
__device__ int   g_bsum[64];
__device__ int   g_csr_src[ET];
__device__ float g_csr_ew[ET];
__device__ __half g_h[(size_t)NN * C256];
__device__ float g_as[NN * NH];
__device__ float g_ad[NN * NH];
__device__ float g_x0[NN * HIDC];
__device__ float g_x1[NN * HIDC];
__device__ float g_vs[HIDC * NH];
__device__ float g_vd[HIDC * NH];
__device__ float g_ce[NH];
// conv3 compaction (only edges feeding the 50 readout targets)
__device__ int   g_tnode[BB];
__device__ int   g_tlen[BB];
__device__ int   g_tpos[BB];
__device__ int   g_ttot;
__device__ int   g_c_src[CAP];
__device__ float g_ch[(size_t)CAP * C256];
__device__ float g_cas[CAP * NH];

__device__ __forceinline__ float elu1(float x)  { return x > 0.f ? x : __expf(x) - 1.f; }
__device__ __forceinline__ float lrelu(float x) { return x > 0.f ? x : 0.2f * x; }

// ------------------------- init -------------------------
__global__ void k_init() {
    int i = blockIdx.x * blockDim.x + threadIdx.x;
    if (i < NN) g_deg[i] = 0;
    if (i == 0) g_ew_sum = 0.f;
}

// ------------------------- edge encoder + dst histogram -------------------------
__global__ void __launch_bounds__(256) k_edge(
    const float* __restrict__ ea, const int* __restrict__ dst,
    const float* __restrict__ w1, const float* __restrict__ b1,
    const float* __restrict__ w2, const float* __restrict__ b2)
{
    __shared__ float ws[448];
    __shared__ float red[8];
    int tid = threadIdx.x;
    for (int i = tid; i < 448; i += 256)
        ws[i] = (i < 320) ? w1[i] : (i < 384) ? b1[i - 320] : w2[i - 384];
    __syncthreads();

    int e = blockIdx.x * 256 + tid;
    float val = 0.f;
    if (e < EE) {
        float a0 = ea[e*5+0], a1 = ea[e*5+1], a2 = ea[e*5+2], a3 = ea[e*5+3], a4 = ea[e*5+4];
        float acc = __ldg(b2);
        #pragma unroll 8
        for (int j = 0; j < 64; j++) {
            float t = ws[320+j] + a0*ws[j] + a1*ws[64+j] + a2*ws[128+j] + a3*ws[192+j] + a4*ws[256+j];
            t = fmaxf(t, 0.f);
            acc += t * ws[384+j];
        }
        val = 1.f / (1.f + __expf(-acc));
        g_ew[e] = val;
        atomicAdd(&g_deg[dst[e]], 1);
    }
    float s = val;
    #pragma unroll
    for (int o = 16; o; o >>= 1) s += __shfl_xor_sync(0xffffffffu, s, o);
    if ((tid & 31) == 0) red[tid >> 5] = s;
    __syncthreads();
    if (tid == 0) {
        float t = 0.f;
        for (int w = 0; w < 8; w++) t += red[w];
        g_ewpart[blockIdx.x] = t;
    }
}

__global__ void k_ewred() {
    __shared__ float red[32];
    int tid = threadIdx.x;
    float s = 0.f;
    for (int i = tid; i < EDGE_BLOCKS; i += 1024) s += g_ewpart[i];
    #pragma unroll
    for (int o = 16; o; o >>= 1) s += __shfl_xor_sync(0xffffffffu, s, o);
    if ((tid & 31) == 0) red[tid >> 5] = s;
    __syncthreads();
    if (tid == 0) {
        float t = 0.f;
        for (int w = 0; w < 32; w++) t += red[w];
        g_ew_sum = t;
    }
}

// ------------------------- CSR build: scan + scatter -------------------------
__global__ void k_scan1() {
    __shared__ int wsum[32];
    int tid = threadIdx.x, lane = tid & 31, w = tid >> 5;
    int i = blockIdx.x * 1024 + tid;
    int x = (i < NN) ? g_deg[i] + 1 : 0;  // +1 for self-loop
    #pragma unroll
    for (int d = 1; d < 32; d <<= 1) {
        int y = __shfl_up_sync(0xffffffffu, x, d);
        if (lane >= d) x += y;
    }
    if (lane == 31) wsum[w] = x;
    __syncthreads();
    if (w == 0) {
        int y = wsum[lane];
        #pragma unroll
        for (int d = 1; d < 32; d <<= 1) {
            int z = __shfl_up_sync(0xffffffffu, y, d);
            if (lane >= d) y += z;
        }
        wsum[lane] = y;
    }
    __syncthreads();
    if (w) x += wsum[w - 1];
    if (i < NN) g_off[i + 1] = x;
    if (tid == 1023) g_bsum[blockIdx.x] = x;
}

__global__ void k_scan2() {
    int running = 0;
    for (int b = 0; b < 49; b++) { int t = g_bsum[b]; g_bsum[b] = running; running += t; }
}

__global__ void k_scan3() {
    int i = blockIdx.x * 1024 + threadIdx.x;
    if (i < NN) g_off[i + 1] += g_bsum[blockIdx.x];
    if (i == 0) g_off[0] = 0;
}

__global__ void k_cursor() {
    int i = blockIdx.x * blockDim.x + threadIdx.x;
    if (i < NN) g_cursor[i] = g_off[i];
}

__global__ void k_scatter(const int* __restrict__ src, const int* __restrict__ dst) {
    int e = blockIdx.x * 256 + threadIdx.x;
    if (e >= EE) return;
    int d = dst[e];
    int p = atomicAdd(&g_cursor[d], 1);
    g_csr_src[p] = src[e];
    g_csr_ew[p]  = g_ew[e];
}

__global__ void k_selfloop() {
    int n = blockIdx.x * blockDim.x + threadIdx.x;
    if (n >= NN) return;
    int p = g_off[n + 1] - 1;
    g_csr_src[p] = n;
    g_csr_ew[p]  = g_ew_sum * (1.f / EE);
}

// ------------------------- target (readout) compaction -------------------------
__global__ void k_tgt(const int* __restrict__ batch) {
    int b = threadIdx.x;
    if (b < BB) {
        int lo = 0, hi = NN;
        while (lo < hi) {
            int mid = (lo + hi) >> 1;
            if (batch[mid] < b) lo = mid + 1; else hi = mid;
        }
        g_tnode[b] = lo;
        g_tlen[b]  = g_off[lo + 1] - g_off[lo];
    }
}

__global__ void k_tpos() {
    int run = 0;
    for (int b = 0; b < BB; b++) { g_tpos[b] = run; run += g_tlen[b]; }
    g_ttot = run < CAP ? run : CAP;
}

__global__ void k_tcopy() {
    int b = blockIdx.x;
    int n = g_tnode[b], st = g_off[n], len = g_tlen[b], p0 = g_tpos[b];
    for (int ii = threadIdx.x; ii < len; ii += 32) {
        int j = p0 + ii;
        if (j < CAP) g_c_src[j] = g_csr_src[st + ii];
    }
}

// ------------------------- per-conv prep: fold att dots into GEMM columns -------------------------
__global__ void k_prep(const float* __restrict__ W, const float* __restrict__ aS,
                       const float* __restrict__ aD, const float* __restrict__ We,
                       const float* __restrict__ aE, int K)
{
    int t = threadIdx.x;
    int k = t >> 2, h = t & 3;
    if (k < K) {
        float s = 0.f, d = 0.f;
        for (int c = 0; c < 64; c++) {
            float wv = W[k * 256 + h * 64 + c];
            s += wv * aS[h * 64 + c];
            d += wv * aD[h * 64 + c];
        }
        g_vs[k * 4 + h] = s;
        g_vd[k * 4 + h] = d;
    }
    if (t < 4) {
        float ce = 0.f;
        for (int c = 0; c < 64; c++) ce += We[t * 64 + c] * aE[t * 64 + c];
        g_ce[t] = ce;
    }
}

// ------------------------- node GEMM: h = xi@W (fp16 out), + fused alpha_src/alpha_dst -------------------------
template <int K>
__global__ void __launch_bounds__(288) k_gemm(int which, const float* __restrict__ xin_ext,
                                              const float* __restrict__ W)
{
    const float* __restrict__ xin = (which == 0) ? g_x0 : (which == 1) ? g_x1 : xin_ext;
    __shared__ __align__(16) float xs[32 * K];
    int tid = threadIdx.x;
    int node0 = blockIdx.x * 32;
    int base = node0 * K;
    for (int i = tid; i < 32 * K; i += 288) {
        int gi = base + i;
        xs[i] = (gi < NN * K) ? xin[gi] : 0.f;
    }
    __syncthreads();

    if (tid < 256) {
        // weights packed two-K-per-64bit for fma.rn.f32x2
        unsigned long long wd[K / 2];
        #pragma unroll
        for (int k2 = 0; k2 < K / 2; k2++) {
            float w0 = W[(2 * k2) * 256 + tid];
            float w1 = W[(2 * k2 + 1) * 256 + tid];
            asm("mov.b64 %0, {%1, %2};" : "=l"(wd[k2]) : "f"(w0), "f"(w1));
        }
        for (int nn = 0; nn < 32; nn++) {
            int node = node0 + nn;
            if (node >= NN) break;
            const ulonglong2* x2 = (const ulonglong2*)(xs + nn * K);
            unsigned long long acc = 0ull;  // packed (0.f, 0.f)
            #pragma unroll
            for (int q = 0; q < K / 4; q++) {
                ulonglong2 v = x2[q];
                asm("fma.rn.f32x2 %0, %1, %2, %0;" : "+l"(acc) : "l"(v.x), "l"(wd[2 * q]));
                asm("fma.rn.f32x2 %0, %1, %2, %0;" : "+l"(acc) : "l"(v.y), "l"(wd[2 * q + 1]));
            }
            float lo, hi;
            asm("mov.b64 {%0, %1}, %2;" : "=f"(lo), "=f"(hi) : "l"(acc));
            g_h[(size_t)node * 256 + tid] = __float2half(lo + hi);
        }
    } else {
        int t2 = tid - 256;
        int role = t2 & 7, h = role & 3, nsub = t2 >> 3;
        const float* v = (role & 4) ? g_vd : g_vs;
        float* outp = (role & 4) ? g_ad : g_as;
        for (int nn = nsub; nn < 32; nn += 4) {
            int node = node0 + nn;
            if (node >= NN) continue;
            float a = 0.f;
            #pragma unroll
            for (int k = 0; k < K; k++) a += xs[nn * K + k] * v[k * 4 + h];
            outp[node * 4 + h] = a;
        }
    }
}

// ------------------------- warp-per-node GAT aggregation (fp16 h gather) -------------------------
__device__ __forceinline__ void warp_agg(int n, int lane, int* s_sm, float4* p_sm, float r[8])
{
    const unsigned F = 0xffffffffu;
    int start = g_off[n], end = g_off[n + 1];
    float4 adv = *(const float4*)(g_ad + n * 4);
    float ce0 = g_ce[0], ce1 = g_ce[1], ce2 = g_ce[2], ce3 = g_ce[3];
    int head = lane >> 3;

    float sl0 = 0.f, sl1 = 0.f, sl2 = 0.f, sl3 = 0.f;
    float acc[8];
    #pragma unroll
    for (int j = 0; j < 8; j++) acc[j] = 0.f;

    for (int base = start; base < end; base += 32) {
        int i = base + lane;
        bool v = i < end;
        int s = v ? g_csr_src[i] : 0;
        float w = v ? g_csr_ew[i] : 0.f;
        float4 asv = *(const float4*)(g_as + s * 4);
        float p0 = v ? __expf(lrelu(asv.x + adv.x + w * ce0)) : 0.f;
        float p1 = v ? __expf(lrelu(asv.y + adv.y + w * ce1)) : 0.f;
        float p2 = v ? __expf(lrelu(asv.z + adv.z + w * ce2)) : 0.f;
        float p3 = v ? __expf(lrelu(asv.w + adv.w + w * ce3)) : 0.f;
        sl0 += p0; sl1 += p1; sl2 += p2; sl3 += p3;

        s_sm[lane] = s;
        p_sm[lane] = make_float4(p0, p1, p2, p3);
        __syncwarp();
        int cnt = min(32, end - base);
        for (int kk = 0; kk < cnt; kk++) {
            int sk = s_sm[kk];
            float pk = ((const float*)p_sm)[kk * 4 + head];
            uint4 hv = *(const uint4*)(g_h + ((size_t)sk << 8) + (lane << 3));
            float2 f0 = __half22float2(*reinterpret_cast<__half2*>(&hv.x));
            float2 f1 = __half22float2(*reinterpret_cast<__half2*>(&hv.y));
            float2 f2 = __half22float2(*reinterpret_cast<__half2*>(&hv.z));
            float2 f3 = __half22float2(*reinterpret_cast<__half2*>(&hv.w));
            acc[0] += pk * f0.x; acc[1] += pk * f0.y;
            acc[2] += pk * f1.x; acc[3] += pk * f1.y;
            acc[4] += pk * f2.x; acc[5] += pk * f2.y;
            acc[6] += pk * f3.x; acc[7] += pk * f3.y;
        }
        __syncwarp();
    }

    #pragma unroll
    for (int o = 16; o; o >>= 1) {
        sl0 += __shfl_xor_sync(F, sl0, o);
        sl1 += __shfl_xor_sync(F, sl1, o);
        sl2 += __shfl_xor_sync(F, sl2, o);
        sl3 += __shfl_xor_sync(F, sl3, o);
    }
    float myS = (lane & 16) ? ((lane & 8) ? sl3 : sl2) : ((lane & 8) ? sl1 : sl0);
    float inv = 1.f / (myS + 1e-16f);
    #pragma unroll
    for (int j = 0; j < 8; j++) {
        float vv = acc[j] * inv;
        vv += __shfl_xor_sync(F, vv, 8);
        vv += __shfl_xor_sync(F, vv, 16);
        r[j] = vv;  // head-sum for channel (lane&7)*8+j
    }
}

__global__ void __launch_bounds__(256) k_agg(int mode, const float* __restrict__ bias)
{
    __shared__ int s_sm[8][32];
    __shared__ float4 p_sm[8][32];
    int lane = threadIdx.x & 31, w = threadIdx.x >> 5;
    int n = blockIdx.x * 8 + w;
    if (n >= NN) return;
    float r[8];
    warp_agg(n, lane, s_sm[w], p_sm[w], r);
    if (lane < 8) {
        const float* res = mode ? g_x0 : nullptr;
        float* outp = mode ? g_x1 : g_x0;
        float o[8];
        #pragma unroll
        for (int j = 0; j < 8; j++) {
            int c = lane * 8 + j;
            float val = 0.25f * r[j] + __ldg(bias + c);
            if (res) val += res[(size_t)n * 64 + c];
            o[j] = elu1(val);
        }
        float4* op = (float4*)(outp + (size_t)n * 64 + lane * 8);
        op[0] = make_float4(o[0], o[1], o[2], o[3]);
        op[1] = make_float4(o[4], o[5], o[6], o[7]);
    }
}

// ------------------------- conv3 compact GEMM over needed edge-sources -------------------------
__global__ void __launch_bounds__(256) k_gemm3c(const float* __restrict__ W)
{
    __shared__ float xr[64];
    __shared__ int s_sh;
    int tot = g_ttot;
    for (int j = blockIdx.x; j < tot; j += gridDim.x) {
        if (threadIdx.x == 0) s_sh = g_c_src[j];
        __syncthreads();
        int s = s_sh;
        if (threadIdx.x < 64) xr[threadIdx.x] = g_x1[(size_t)s * 64 + threadIdx.x];
        __syncthreads();
        int t = threadIdx.x;
        float acc = 0.f;
        #pragma unroll
        for (int k = 0; k < 64; k++) acc += xr[k] * __ldg(W + k * 256 + t);
        g_ch[(size_t)j * 256 + t] = acc;
        if (t < 4) {
            float a = 0.f;
            #pragma unroll
            for (int k = 0; k < 64; k++) a += xr[k] * g_vs[k * 4 + t];
            g_cas[j * 4 + t] = a;
        }
        __syncthreads();
    }
}

// ------------------------- conv3 @ targets + LayerNorm + MLP readout -------------------------
__global__ void __launch_bounds__(32) k_final(
    const float* __restrict__ bias,
    const float* __restrict__ lng, const float* __restrict__ lnb,
    const float* __restrict__ l1w, const float* __restrict__ l1b,
    const float* __restrict__ l2w, const float* __restrict__ l2b,
    float* __restrict__ out)
{
    __shared__ float4 p_s[32];
    __shared__ float xnode[64], advs[4], xbuf[64], tbuf[64];
    const unsigned F = 0xffffffffu;
    int lane = threadIdx.x;
    int b = blockIdx.x;

    int n = g_tnode[b];
    int start = g_off[n];
    int len = g_tlen[b];
    int posb = g_tpos[b];

    xnode[lane]      = g_x1[(size_t)n * 64 + lane];
    xnode[lane + 32] = g_x1[(size_t)n * 64 + lane + 32];
    __syncwarp();

    if (lane < 4) {
        float a = 0.f;
        #pragma unroll
        for (int k = 0; k < 64; k++) a += xnode[k] * g_vd[k * 4 + lane];
        advs[lane] = a;
    }
    __syncwarp();

    float4 adv = make_float4(advs[0], advs[1], advs[2], advs[3]);
    float ce0 = g_ce[0], ce1 = g_ce[1], ce2 = g_ce[2], ce3 = g_ce[3];
    int head = lane >> 3;

    float sl0 = 0.f, sl1 = 0.f, sl2 = 0.f, sl3 = 0.f;
    float acc[8];
    #pragma unroll
    for (int j = 0; j < 8; j++) acc[j] = 0.f;

    for (int base = 0; base < len; base += 32) {
        int ii = base + lane;
        bool v = ii < len;
        float w = v ? g_csr_ew[start + ii] : 0.f;
        int jj = posb + ii;
        float4 asv = v ? *(const float4*)(g_cas + jj * 4) : make_float4(0, 0, 0, 0);
        float p0 = v ? __expf(lrelu(asv.x + adv.x + w * ce0)) : 0.f;
        float p1 = v ? __expf(lrelu(asv.y + adv.y + w * ce1)) : 0.f;
        float p2 = v ? __expf(lrelu(asv.z + adv.z + w * ce2)) : 0.f;
        float p3 = v ? __expf(lrelu(asv.w + adv.w + w * ce3)) : 0.f;
        sl0 += p0; sl1 += p1; sl2 += p2; sl3 += p3;
        p_s[lane] = make_float4(p0, p1, p2, p3);
        __syncwarp();
        int cnt = min(32, len - base);
        for (int kk = 0; kk < cnt; kk++) {
            int jk = posb + base + kk;
            float pk = ((const float*)p_s)[kk * 4 + head];
            const float4* hp = (const float4*)(g_ch + (size_t)jk * 256 + lane * 8);
            float4 h0 = hp[0], h1 = hp[1];
            acc[0] += pk * h0.x; acc[1] += pk * h0.y; acc[2] += pk * h0.z; acc[3] += pk * h0.w;
            acc[4] += pk * h1.x; acc[5] += pk * h1.y; acc[6] += pk * h1.z; acc[7] += pk * h1.w;
        }
        __syncwarp();
    }

    #pragma unroll
    for (int o = 16; o; o >>= 1) {
        sl0 += __shfl_xor_sync(F, sl0, o);
        sl1 += __shfl_xor_sync(F, sl1, o);
        sl2 += __shfl_xor_sync(F, sl2, o);
        sl3 += __shfl_xor_sync(F, sl3, o);
    }
    float myS = (lane & 16) ? ((lane & 8) ? sl3 : sl2) : ((lane & 8) ? sl1 : sl0);
    float inv = 1.f / (myS + 1e-16f);
    float r[8];
    #pragma unroll
    for (int j = 0; j < 8; j++) {
        float vv = acc[j] * inv;
        vv += __shfl_xor_sync(F, vv, 8);
        vv += __shfl_xor_sync(F, vv, 16);
        r[j] = vv;
    }

    if (lane < 8) {
        #pragma unroll
        for (int j = 0; j < 8; j++) {
            int c = lane * 8 + j;
            float val = 0.25f * r[j] + bias[c] + xnode[c];
            xbuf[c] = elu1(val);
        }
    }
    __syncwarp();

    float v0 = xbuf[lane], v1 = xbuf[lane + 32];
    float sum = v0 + v1;
    #pragma unroll
    for (int o = 16; o; o >>= 1) sum += __shfl_xor_sync(F, sum, o);
    float mean = sum * (1.f / 64.f);
    float d0 = v0 - mean, d1 = v1 - mean;
    float vs = d0 * d0 + d1 * d1;
    #pragma unroll
    for (int o = 16; o; o >>= 1) vs += __shfl_xor_sync(F, vs, o);
    float rstd = rsqrtf(vs * (1.f / 64.f) + 1e-5f);
    xbuf[lane]      = d0 * rstd * lng[lane]      + lnb[lane];
    xbuf[lane + 32] = d1 * rstd * lng[lane + 32] + lnb[lane + 32];
    __syncwarp();

    float a0 = l1b[lane], a1 = l1b[lane + 32];
    for (int c = 0; c < 64; c++) {
        float xv = xbuf[c];
        a0 += xv * l1w[c * 64 + lane];
        a1 += xv * l1w[c * 64 + lane + 32];
    }
    tbuf[lane]      = elu1(a0);
    tbuf[lane + 32] = elu1(a1);
    __syncwarp();

    if (lane < 3) {
        float o = l2b[lane];
        for (int c = 0; c < 64; c++) o += tbuf[c] * l2w[c * 3 + lane];
        out[b * 3 + lane] = o;
    }
}

// ------------------------- launch -------------------------
extern "C" void kernel_launch(void* const* d_in, const int* in_sizes, int n_in,
                              void* d_out, int out_size)
{
    const float* x      = (const float*)d_in[0];
    const int*   ei     = (const int*)  d_in[1];
    const float* eattr  = (const float*)d_in[2];
    const int*   batch  = (const int*)  d_in[3];
    const float* ee_w1  = (const float*)d_in[4];
    const float* ee_b1  = (const float*)d_in[5];
    const float* ee_w2  = (const float*)d_in[6];
    const float* ee_b2  = (const float*)d_in[7];
    const float* W1     = (const float*)d_in[8];
    const float* Ws     = (const float*)d_in[9];
    const float* att_s  = (const float*)d_in[10];
    const float* att_d  = (const float*)d_in[11];
    const float* We     = (const float*)d_in[12];
    const float* att_e  = (const float*)d_in[13];
    const float* bias   = (const float*)d_in[14];
    const float* lng    = (const float*)d_in[15];
    const float* lnb    = (const float*)d_in[16];
    const float* l1w    = (const float*)d_in[17];
    const float* l1b    = (const float*)d_in[18];
    const float* l2w    = (const float*)d_in[19];
    const float* l2b    = (const float*)d_in[20];
    float* out = (float*)d_out;

    const int* src = ei;
    const int* dst = ei + EE;

    k_init<<<(NN + 255) / 256, 256>>>();
    k_edge<<<EDGE_BLOCKS, 256>>>(eattr, dst, ee_w1, ee_b1, ee_w2, ee_b2);
    k_ewred<<<1, 1024>>>();
    k_scan1<<<49, 1024>>>();
    k_scan2<<<1, 1>>>();
    k_scan3<<<49, 1024>>>();
    k_cursor<<<(NN + 255) / 256, 256>>>();
    k_scatter<<<EDGE_BLOCKS, 256>>>(src, dst);
    k_selfloop<<<(NN + 255) / 256, 256>>>();

    // readout-target compaction metadata
    k_tgt<<<1, 64>>>(batch);
    k_tpos<<<1, 1>>>();
    k_tcopy<<<BB, 32>>>();

    const int gemm_grid = (NN + 31) / 32;
    const int agg_grid  = (NN + 7) / 8;

    // conv1: x [N,16] -> xi0
    k_prep<<<1, 256>>>(W1, att_s, att_d, We, att_e, FIN);
    k_gemm<FIN><<<gemm_grid, 288>>>(-1, x, W1);
    k_agg<<<agg_grid, 256>>>(0, bias);

    // conv2 (residual): xi0 -> xi1
    k_prep<<<1, 256>>>(Ws, att_s + 256, att_d + 256, We + 256, att_e + 256, HIDC);
    k_gemm<HIDC><<<gemm_grid, 288>>>(0, nullptr, Ws);
    k_agg<<<agg_grid, 256>>>(1, bias + 64);

    // conv3 (residual) only at the 50 readout targets, via compact edge-source list
    k_prep<<<1, 256>>>(Ws + 64 * 256, att_s + 512, att_d + 512, We + 512, att_e + 512, HIDC);
    k_gemm3c<<<1024, 256>>>(Ws + 64 * 256);
    k_final<<<BB, 32>>>(bias + 128, lng, lnb, l1w, l1b, l2w, l2b, out);
}